// round 1
// baseline (speedup 1.0000x reference)
#include <cuda_runtime.h>
#include <math.h>

#define Bq    64
#define NEV   512
#define KDIM  128
#define HDIM  512
#define G7    3584   /* 7*HDIM */

// ---------------- persistent device scratch (no allocations allowed) ----------------
__device__ int   g_marks[Bq * NEV];
__device__ float g_dt[Bq * NEV];
__device__ float g_ht[2][Bq * HDIM];   // double-buffered hidden state by step parity
__device__ float g_ct[Bq * HDIM];
__device__ float g_cbar[Bq * HDIM];

// ---------------- prep: marks (one-hot -> index), dt, zero init ----------------
__global__ void prep_kernel(const float* __restrict__ seq,
                            const float* __restrict__ times)
{
    int tid = blockIdx.x * blockDim.x + threadIdx.x;
    int nt  = gridDim.x * blockDim.x;

    for (int i = tid; i < Bq * NEV; i += nt) {
        int b = i / NEV;
        int n = i - b * NEV;
        const float* s = seq + (size_t)i * KDIM;
        int m = 0;
        #pragma unroll 4
        for (int k = 0; k < KDIM; k++) {
            if (s[k] > 0.5f) m = k;
        }
        g_marks[i] = m;
        g_dt[i] = times[b * (NEV + 1) + n + 1] - times[b * (NEV + 1) + n];
    }
    for (int i = tid; i < Bq * HDIM; i += nt) {
        g_ht[0][i] = 0.f;
        g_ct[i]    = 0.f;
        g_cbar[i]  = 0.f;
    }
}

__device__ __forceinline__ float sigf(float x) { return 1.0f / (1.0f + expf(-x)); }

// ---------------- one recurrence step ----------------
// Grid: 64 CTAs = 8 column-tiles (64 state cols each) x 8 batch-tiles (8 batches each).
// Each CTA computes g = ht_{t-1} @ W_V slice (448 gate cols) and, fused as extra
// columns, lamb_til_{t-1} = ht_{t-1} @ W_lamb slice (16 cols). Then the gate math /
// state update / output writes for its (cols x batches) block.
// Launched for t = 0..512; t==512 only emits the final lamb.
__global__ __launch_bounds__(128) void step_kernel(
    const float* __restrict__ W_U,  const float* __restrict__ b_U,
    const float* __restrict__ W_V,  const float* __restrict__ b_V,
    const float* __restrict__ W_lamb, const float* __restrict__ b_lamb,
    const float* __restrict__ scale,
    float* __restrict__ out, int t)
{
    __shared__ __align__(16) float ht_sm[8][HDIM];   // 16 KB
    __shared__ __align__(16) float w_sm[16][468];    // 29.25 KB (464 used cols + pad)

    const int tid   = threadIdx.x;
    const int jq    = tid & 15;        // column quad 0..15 (4 state cols each)
    const int bl    = tid >> 4;        // local batch 0..7
    const int ctile = blockIdx.x & 7;  // column tile 0..7
    const int btile = blockIdx.x >> 3; // batch tile 0..7
    const int bg    = btile * 8 + bl;  // global batch
    const int par   = t & 1;

    // stage ht_{t-1} for this batch tile
    {
        const float4* src = reinterpret_cast<const float4*>(g_ht[par] + (size_t)(btile * 8) * HDIM);
        float4* dst = reinterpret_cast<float4*>(&ht_sm[0][0]);
        #pragma unroll 4
        for (int i = tid; i < (8 * HDIM) / 4; i += 128) dst[i] = src[i];
    }

    float acc[7][4];
    #pragma unroll
    for (int g = 0; g < 7; g++) {
        acc[g][0] = 0.f; acc[g][1] = 0.f; acc[g][2] = 0.f; acc[g][3] = 0.f;
    }
    float accL = 0.f;  // lamb column jq

    const int colW = ctile * 64;   // base of this tile's 64 state cols
    const int colL = ctile * 16;   // base of this tile's 16 lamb cols

    for (int kc = 0; kc < 32; kc++) {
        const int kbase = kc * 16;

        __syncthreads();   // previous chunk's reads done (also orders ht_sm at kc==0)
        // stage W chunk: rows 0..447 = W_V (gate g, state col j -> r = g*64+j),
        //                rows 448..463 = W_lamb cols
        #pragma unroll 4
        for (int e = tid; e < 464 * 16; e += 128) {
            int kk = e / 464;
            int r  = e - kk * 464;
            int k  = kbase + kk;
            float v;
            if (r < 448) {
                v = W_V[(size_t)k * G7 + (r >> 6) * HDIM + colW + (r & 63)];
            } else {
                v = W_lamb[k * KDIM + colL + (r - 448)];
            }
            w_sm[kk][r] = v;
        }
        __syncthreads();

        #pragma unroll
        for (int kk = 0; kk < 16; kk++) {
            float h = ht_sm[bl][kbase + kk];
            accL = fmaf(h, w_sm[kk][448 + jq], accL);
            #pragma unroll
            for (int g = 0; g < 7; g++) {
                float4 w = *reinterpret_cast<const float4*>(&w_sm[kk][g * 64 + jq * 4]);
                acc[g][0] = fmaf(h, w.x, acc[g][0]);
                acc[g][1] = fmaf(h, w.y, acc[g][1]);
                acc[g][2] = fmaf(h, w.z, acc[g][2]);
                acc[g][3] = fmaf(h, w.w, acc[g][3]);
            }
        }
    }

    // output tensor layout: lamb | CLow | Cbar | delta | OutGate (concatenated)
    const size_t BNK = (size_t)Bq * NEV * KDIM;
    const size_t BNH = (size_t)Bq * NEV * HDIM;
    float* outLamb  = out;
    float* outClow  = out + BNK;
    float* outCbar  = out + BNK + BNH;
    float* outDelta = out + BNK + 2 * BNH;
    float* outO     = out + BNK + 3 * BNH;

    // lamb for step t-1 (uses ht_{t-1}, which is what we just multiplied)
    if (t >= 1) {
        int lc = colL + jq;
        float ltil = accL + b_lamb[lc];
        float s = scale[lc];
        float x = ltil / s;
        float sp = fmaxf(x, 0.f) + log1pf(expf(-fabsf(x)));
        outLamb[((size_t)bg * NEV + (t - 1)) * KDIM + lc] = s * sp;
    }

    // gate math + state update for step t
    if (t < NEV) {
        int   mark = g_marks[bg * NEV + t];
        float dtv  = g_dt[bg * NEV + t];
        const float* wu = W_U + (size_t)mark * G7;
        int col0 = colW + jq * 4;

        float4 ctv = *reinterpret_cast<const float4*>(&g_ct[(size_t)bg * HDIM + col0]);
        float4 cbv = *reinterpret_cast<const float4*>(&g_cbar[(size_t)bg * HDIM + col0]);
        float ctArr[4] = {ctv.x, ctv.y, ctv.z, ctv.w};
        float cbArr[4] = {cbv.x, cbv.y, cbv.z, cbv.w};

        float clowA[4], cbnA[4], deltA[4], ogA[4], htnA[4], ctnA[4];

        #pragma unroll
        for (int c = 0; c < 4; c++) {
            int col = col0 + c;
            float gg[7];
            #pragma unroll
            for (int g = 0; g < 7; g++) {
                int gc = g * HDIM + col;
                gg[g] = acc[g][c] + wu[gc] + b_U[gc] + b_V[gc];
            }
            float vi  = sigf(gg[0]);
            float vf  = sigf(gg[1]);
            float viB = sigf(gg[2]);
            float vfB = sigf(gg[3]);
            float vz  = 2.0f * sigf(gg[4]);
            float vo  = sigf(gg[5]);
            float vd  = (gg[6] > 0.f) ? gg[6] : 0.01f * gg[6];

            float cl  = vf * ctArr[c] + vi * vz;
            float cbn = vfB * cbArr[c] + viB * vz;
            float ctn = cbn + (cl - cbn) * expf(dtv * vd);
            float htn = vo * (2.0f * sigf(2.0f * ctn) - 1.0f);

            clowA[c] = cl; cbnA[c] = cbn; deltA[c] = vd; ogA[c] = vo;
            ctnA[c] = ctn; htnA[c] = htn;
        }

        // persist state
        *reinterpret_cast<float4*>(&g_ct[(size_t)bg * HDIM + col0]) =
            make_float4(ctnA[0], ctnA[1], ctnA[2], ctnA[3]);
        *reinterpret_cast<float4*>(&g_cbar[(size_t)bg * HDIM + col0]) =
            make_float4(cbnA[0], cbnA[1], cbnA[2], cbnA[3]);
        *reinterpret_cast<float4*>(&g_ht[par ^ 1][(size_t)bg * HDIM + col0]) =
            make_float4(htnA[0], htnA[1], htnA[2], htnA[3]);

        // outputs for step t
        size_t ob = ((size_t)bg * NEV + t) * HDIM + col0;
        *reinterpret_cast<float4*>(&outClow[ob])  = make_float4(clowA[0], clowA[1], clowA[2], clowA[3]);
        *reinterpret_cast<float4*>(&outCbar[ob])  = make_float4(cbnA[0],  cbnA[1],  cbnA[2],  cbnA[3]);
        *reinterpret_cast<float4*>(&outDelta[ob]) = make_float4(deltA[0], deltA[1], deltA[2], deltA[3]);
        *reinterpret_cast<float4*>(&outO[ob])     = make_float4(ogA[0],   ogA[1],   ogA[2],   ogA[3]);
    }
}

// ---------------- launch ----------------
extern "C" void kernel_launch(void* const* d_in, const int* in_sizes, int n_in,
                              void* d_out, int out_size)
{
    const float* seq    = (const float*)d_in[0];
    const float* times  = (const float*)d_in[1];
    const float* W_U    = (const float*)d_in[2];
    const float* b_U    = (const float*)d_in[3];
    const float* W_V    = (const float*)d_in[4];
    const float* b_V    = (const float*)d_in[5];
    const float* W_lamb = (const float*)d_in[6];
    const float* b_lamb = (const float*)d_in[7];
    const float* scale  = (const float*)d_in[8];
    float* out = (float*)d_out;

    prep_kernel<<<64, 256>>>(seq, times);

    // t = 0..511: recurrence step t (+ lamb for t-1). t = 512: final lamb only.
    for (int t = 0; t <= NEV; t++) {
        step_kernel<<<64, 128>>>(W_U, b_U, W_V, b_V, W_lamb, b_lamb, scale, out, t);
    }
}

// round 2
// speedup vs baseline: 2.3341x; 2.3341x over previous
#include <cuda_runtime.h>
#include <math.h>

#define Bq    64
#define NEV   512
#define KDIM  128
#define HDIM  512
#define G7    3584
#define NCTA  128
#define NTH   256
#define WST   30            /* w_sm row stride in floats */
#define PST   264           /* partial buffer inner stride in u64 (8*33) */

typedef unsigned long long u64;

// ---------------- persistent device scratch ----------------
__device__ int      g_marks[Bq * NEV];
__device__ float    g_dt[Bq * NEV];
__device__ float    g_htT[2][HDIM * Bq];   // [parity][col][batch]
__device__ unsigned g_arrive;
__device__ unsigned g_release;

// ---------------- helpers ----------------
__device__ __forceinline__ u64 ffma2(u64 a, u64 b, u64 c) {
    u64 d;
    asm("fma.rn.f32x2 %0, %1, %2, %3;" : "=l"(d) : "l"(a), "l"(b), "l"(c));
    return d;
}
__device__ __forceinline__ u64 pack2(float lo, float hi) {
    u64 d;
    asm("mov.b64 %0, {%1, %2};" : "=l"(d) : "f"(lo), "f"(hi));
    return d;
}
__device__ __forceinline__ float2 unpack2(u64 v) {
    float2 r;
    asm("mov.b64 {%0, %1}, %2;" : "=f"(r.x), "=f"(r.y) : "l"(v));
    return r;
}
__device__ __forceinline__ float sigf(float x) { return 1.0f / (1.0f + expf(-x)); }

// ---------------- prep ----------------
__global__ void prep_kernel(const float* __restrict__ seq,
                            const float* __restrict__ times)
{
    int tid = blockIdx.x * blockDim.x + threadIdx.x;
    int nt  = gridDim.x * blockDim.x;
    if (tid == 0) { g_arrive = 0u; g_release = 0u; }

    for (int i = tid; i < Bq * NEV; i += nt) {
        int b = i / NEV;
        int n = i - b * NEV;
        const float* s = seq + (size_t)i * KDIM;
        int m = 0;
        #pragma unroll 4
        for (int k = 0; k < KDIM; k++) if (s[k] > 0.5f) m = k;
        g_marks[i] = m;
        g_dt[i] = times[b * (NEV + 1) + n + 1] - times[b * (NEV + 1) + n];
    }
    for (int i = tid; i < 2 * HDIM * Bq; i += nt)
        g_htT[0][i] = 0.f;   // zeroes both parities (contiguous)
}

// ---------------- SMEM layout (dynamic) ----------------
#define OFF_W     0                     /* 512*30*4   = 61440  */
#define OFF_PART  61440                 /* 29*264*8   = 61248  */
#define OFF_GSUM  122688                /* 32*29*8    = 7424   */
#define OFF_CT    130112                /* 4*64*4     = 1024   */
#define OFF_CBAR  131136                /* 1024               */
#define OFF_BIAS  132160                /* 32*4 = 128         */
#define SMEM_TOT  132288

// ---------------- persistent kernel ----------------
// CTA c owns state cols j0=4c..4c+3 (-> 28 gate cols) and lamb col c.
__global__ __launch_bounds__(NTH, 1) void persist_kernel(
    const float* __restrict__ W_U,  const float* __restrict__ b_U,
    const float* __restrict__ W_V,  const float* __restrict__ b_V,
    const float* __restrict__ W_lamb, const float* __restrict__ b_lamb,
    const float* __restrict__ scale,
    float* __restrict__ out)
{
    extern __shared__ char smem_raw[];
    float*  w_sm    = (float*)(smem_raw + OFF_W);
    u64*    part    = (u64*)  (smem_raw + OFF_PART);
    float2* gsum    = (float2*)(smem_raw + OFF_GSUM);
    float*  ct_sm   = (float*)(smem_raw + OFF_CT);
    float*  cbar_sm = (float*)(smem_raw + OFF_CBAR);
    float*  bias_sm = (float*)(smem_raw + OFF_BIAS);

    const int tid = threadIdx.x;
    const int c   = blockIdx.x;
    const int j0  = c * 4;

    // ---- one-time init: load W slice, biases, zero state ----
    for (int idx = tid; idx < 512 * 29; idx += NTH) {
        int k = idx / 29, r = idx - k * 29;
        float v;
        if (r < 28) {
            int p = r >> 1, e = r & 1;      // p = g*2 + cp
            int g = p >> 1, cp = p & 1;
            v = W_V[(size_t)k * G7 + g * HDIM + j0 + 2 * cp + e];
        } else {
            v = W_lamb[k * KDIM + c];
        }
        w_sm[k * WST + r] = v;
    }
    if (tid < 28) {
        int p = tid >> 1, e = tid & 1;
        int g = p >> 1, cp = p & 1;
        int col = g * HDIM + j0 + 2 * cp + e;
        bias_sm[tid] = b_U[col] + b_V[col];
    }
    if (tid == 28) bias_sm[28] = b_lamb[c];
    if (tid == 29) bias_sm[29] = scale[c];
    for (int i = tid; i < 4 * Bq; i += NTH) { ct_sm[i] = 0.f; cbar_sm[i] = 0.f; }
    __syncthreads();

    // output tensor views: lamb | CLow | Cbar | delta | OutGate
    const size_t BNK = (size_t)Bq * NEV * KDIM;
    const size_t BNH = (size_t)Bq * NEV * HDIM;
    float* outLamb  = out;
    float* outClow  = out + BNK;
    float* outCbar  = out + BNK + BNH;
    float* outDelta = out + BNK + 2 * BNH;
    float* outO     = out + BNK + 3 * BNH;

    const int s  = tid & 7;     // k-split 0..7 (64 k each)
    const int b2 = tid >> 3;    // batch pair 0..31
    const int k0 = s * 64;

    const int je = tid >> 6;    // epilogue: state col 0..3
    const int be = tid & 63;    // epilogue: batch

    for (int t = 0; t <= NEV; t++) {
        const int par = t & 1;
        const float2* htp = (const float2*)g_htT[par];   // [k][32 pairs]

        // ---------------- GEMM: partial sums over k-range ----------------
        u64 acc[2][14];
        #pragma unroll
        for (int bl = 0; bl < 2; bl++)
            #pragma unroll
            for (int p = 0; p < 14; p++) acc[bl][p] = 0ull;
        u64 accL = 0ull;

        float2 hb[4];
        #pragma unroll
        for (int i = 0; i < 4; i++)
            hb[i] = __ldcg(&htp[(k0 + i) * 32 + b2]);

        #pragma unroll 4
        for (int kk = 0; kk < 64; kk++) {
            const int k = k0 + kk;
            float2 h = hb[kk & 3];
            int kn = k + 4; if (kn > 511) kn = 511;
            hb[kk & 3] = __ldcg(&htp[kn * 32 + b2]);

            u64 h0 = pack2(h.x, h.x);
            u64 h1 = pack2(h.y, h.y);
            const u64* wr = (const u64*)(w_sm + k * WST);
            #pragma unroll
            for (int p = 0; p < 14; p++) {
                u64 w = wr[p];
                acc[0][p] = ffma2(h0, w, acc[0][p]);
                acc[1][p] = ffma2(h1, w, acc[1][p]);
            }
            float wl = w_sm[k * WST + 28];
            accL = ffma2(pack2(h.x, h.y), pack2(wl, wl), accL);
        }

        // ---------------- store partials ----------------
        {
            u64* pb = part + (s * 33 + b2);
            #pragma unroll
            for (int bl = 0; bl < 2; bl++)
                #pragma unroll
                for (int p = 0; p < 14; p++)
                    pb[(bl * 14 + p) * PST] = acc[bl][p];
            pb[28 * PST] = accL;
        }
        __syncthreads();

        // ---------------- reduce over s ----------------
        for (int r = tid; r < 29 * 32; r += NTH) {
            int tag = r >> 5, bb = r & 31;
            const u64* pp = part + tag * PST + bb;
            float2 sm = make_float2(0.f, 0.f);
            #pragma unroll
            for (int ss = 0; ss < 8; ss++) {
                float2 v = unpack2(pp[ss * 33]);
                sm.x += v.x; sm.y += v.y;
            }
            gsum[bb * 29 + tag] = sm;
        }
        __syncthreads();

        // ---------------- epilogue ----------------
        // lamb for step t-1 (computed from ht_{t-1})
        if (t >= 1 && je == 0) {
            float2 lp = gsum[(be >> 1) * 29 + 28];
            float ltil = ((be & 1) ? lp.y : lp.x) + bias_sm[28];
            float sc = bias_sm[29];
            float x = ltil / sc;
            float sp = fmaxf(x, 0.f) + log1pf(expf(-fabsf(x)));
            outLamb[((size_t)be * NEV + (t - 1)) * KDIM + c] = sc * sp;
        }

        if (t < NEV) {
            const int col = j0 + je;
            const int bl = be & 1, bh = be >> 1;
            const int cp = je >> 1, e = je & 1;
            int   mark = g_marks[be * NEV + t];
            float dtv  = g_dt[be * NEV + t];
            const float* wu = W_U + (size_t)mark * G7;

            float gg[7];
            #pragma unroll
            for (int g = 0; g < 7; g++) {
                int p = g * 2 + cp;
                float2 v = gsum[bh * 29 + (bl * 14 + p)];
                float a = e ? v.y : v.x;
                gg[g] = a + wu[g * HDIM + col] + bias_sm[p * 2 + e];
            }

            float vi  = sigf(gg[0]);
            float vf  = sigf(gg[1]);
            float viB = sigf(gg[2]);
            float vfB = sigf(gg[3]);
            float vz  = 2.0f * sigf(gg[4]);
            float vo  = sigf(gg[5]);
            float vd  = (gg[6] > 0.f) ? gg[6] : 0.01f * gg[6];

            int si = je * Bq + be;
            float cl  = vf * ct_sm[si] + vi * vz;
            float cbn = vfB * cbar_sm[si] + viB * vz;
            float ctn = cbn + (cl - cbn) * expf(dtv * vd);
            float htn = vo * (2.0f * sigf(2.0f * ctn) - 1.0f);

            ct_sm[si]   = ctn;
            cbar_sm[si] = cbn;
            g_htT[par ^ 1][col * Bq + be] = htn;

            size_t ob = ((size_t)be * NEV + t) * HDIM + col;
            outClow[ob]  = cl;
            outCbar[ob]  = cbn;
            outDelta[ob] = vd;
            outO[ob]     = vo;
        }

        // ---------------- grid barrier (skip after final iteration) ----------------
        if (t < NEV) {
            __syncthreads();
            if (tid == 0) {
                __threadfence();
                unsigned tgt = (unsigned)(t + 1) * NCTA;
                unsigned prev = atomicAdd(&g_arrive, 1u);
                if (prev + 1u == tgt) {
                    atomicExch(&g_release, tgt);
                } else {
                    while (*((volatile unsigned*)&g_release) < tgt) { }
                }
                __threadfence();
            }
            __syncthreads();
        }
    }
}

// ---------------- launch ----------------
extern "C" void kernel_launch(void* const* d_in, const int* in_sizes, int n_in,
                              void* d_out, int out_size)
{
    const float* seq    = (const float*)d_in[0];
    const float* times  = (const float*)d_in[1];
    const float* W_U    = (const float*)d_in[2];
    const float* b_U    = (const float*)d_in[3];
    const float* W_V    = (const float*)d_in[4];
    const float* b_V    = (const float*)d_in[5];
    const float* W_lamb = (const float*)d_in[6];
    const float* b_lamb = (const float*)d_in[7];
    const float* scale  = (const float*)d_in[8];
    float* out = (float*)d_out;

    static int attr_done = 0;
    if (!attr_done) {
        cudaFuncSetAttribute(persist_kernel,
                             cudaFuncAttributeMaxDynamicSharedMemorySize, SMEM_TOT);
        attr_done = 1;
    }

    prep_kernel<<<64, 256>>>(seq, times);
    persist_kernel<<<NCTA, NTH, SMEM_TOT>>>(W_U, b_U, W_V, b_V,
                                            W_lamb, b_lamb, scale, out);
}

// round 3
// speedup vs baseline: 14.5409x; 6.2299x over previous
#include <cuda_runtime.h>
#include <math.h>

#define Bq    64
#define NEV   512
#define KDIM  128
#define HDIM  512
#define G7    3584
#define NCTA  128
#define NTH   256
#define WST   30      /* w_sm row stride (floats), 8B-aligned rows */
#define JST   17      /* partial j-stride (u64) */
#define SST   987     /* partial s-stride (u64), odd -> conflict-spread */

typedef unsigned long long u64;

// ---------------- persistent device scratch ----------------
__device__ int      g_marks[Bq * NEV];
__device__ float    g_dt[Bq * NEV];
__device__ float    g_htb[2][Bq * HDIM];   // [parity][batch][k]
__device__ unsigned g_arrive;
__device__ unsigned g_release;

// ---------------- helpers ----------------
__device__ __forceinline__ u64 ffma2(u64 a, u64 b, u64 c) {
    u64 d;
    asm("fma.rn.f32x2 %0, %1, %2, %3;" : "=l"(d) : "l"(a), "l"(b), "l"(c));
    return d;
}
__device__ __forceinline__ u64 pack2(float lo, float hi) {
    u64 d;
    asm("mov.b64 %0, {%1, %2};" : "=l"(d) : "f"(lo), "f"(hi));
    return d;
}
__device__ __forceinline__ float2 unpack2(u64 v) {
    float2 r;
    asm("mov.b64 {%0, %1}, %2;" : "=f"(r.x), "=f"(r.y) : "l"(v));
    return r;
}
__device__ __forceinline__ float sigf(float x) { return 1.0f / (1.0f + expf(-x)); }

// ---------------- prep ----------------
__global__ void prep_kernel(const float* __restrict__ seq,
                            const float* __restrict__ times)
{
    int tid = blockIdx.x * blockDim.x + threadIdx.x;
    int nt  = gridDim.x * blockDim.x;
    if (tid == 0) { g_arrive = 0u; g_release = 0u; }

    for (int i = tid; i < Bq * NEV; i += nt) {
        int b = i / NEV;
        int n = i - b * NEV;
        const float* s = seq + (size_t)i * KDIM;
        int m = 0;
        #pragma unroll 4
        for (int k = 0; k < KDIM; k++) if (s[k] > 0.5f) m = k;
        g_marks[i] = m;
        g_dt[i] = times[b * (NEV + 1) + n + 1] - times[b * (NEV + 1) + n];
    }
    for (int i = tid; i < 2 * Bq * HDIM; i += nt)
        g_htb[0][i] = 0.f;   // contiguous zero of both parities
}

// ---------------- SMEM layout (dynamic, bytes) ----------------
#define OFF_W     0                         /* 512*30*4      = 61440  */
#define OFF_PART  61440                     /* 16*987*8      = 126336 */
#define OFF_GSUM  (61440 + 126336)          /* 928*8         = 7424   */
#define OFF_BIAS  (OFF_GSUM + 7424)         /* 32*4          = 128    */
#define SMEM_TOT  (OFF_BIAS + 128)          /* 195328 */

// ---------------- persistent kernel ----------------
// CTA c owns state cols j0=4c..4c+3 (28 gate cols) + lamb col c.
// GEMM: thread (s = tid&15, bg = tid>>4): k-slice {kk*16+s}, batches bg*4..bg*4+3.
// Epilogue: thread (je = tid&3, be = tid>>2): output col j0+je, batch be.
__global__ __launch_bounds__(NTH, 1) void persist_kernel(
    const float* __restrict__ W_U,  const float* __restrict__ b_U,
    const float* __restrict__ W_V,  const float* __restrict__ b_V,
    const float* __restrict__ W_lamb, const float* __restrict__ b_lamb,
    const float* __restrict__ scale,
    float* __restrict__ out)
{
    extern __shared__ char smem_raw[];
    float* w_sm    = (float*)(smem_raw + OFF_W);
    u64*   part    = (u64*)  (smem_raw + OFF_PART);
    u64*   gsum    = (u64*)  (smem_raw + OFF_GSUM);
    float* bias_sm = (float*)(smem_raw + OFF_BIAS);

    const int tid = threadIdx.x;
    const int c   = blockIdx.x;
    const int j0  = c * 4;

    // ---- one-time init: W slice + biases ----
    for (int idx = tid; idx < 512 * 29; idx += NTH) {
        int k = idx / 29, r = idx - k * 29;
        float v;
        if (r < 28) {
            int p = r >> 1, e = r & 1;      // p = g*2 + cp
            int g = p >> 1, cp = p & 1;
            v = W_V[(size_t)k * G7 + g * HDIM + j0 + 2 * cp + e];
        } else {
            v = W_lamb[k * KDIM + c];
        }
        w_sm[k * WST + r] = v;
    }
    if (tid < 28) {
        int p = tid >> 1, e = tid & 1;
        int g = p >> 1, cp = p & 1;
        int col = g * HDIM + j0 + 2 * cp + e;
        bias_sm[tid] = b_U[col] + b_V[col];
    }
    if (tid == 28) bias_sm[28] = b_lamb[c];
    if (tid == 29) bias_sm[29] = scale[c];
    __syncthreads();

    // output views: lamb | CLow | Cbar | delta | OutGate
    const size_t BNK = (size_t)Bq * NEV * KDIM;
    const size_t BNH = (size_t)Bq * NEV * HDIM;
    float* outLamb  = out;
    float* outClow  = out + BNK;
    float* outCbar  = out + BNK + BNH;
    float* outDelta = out + BNK + 2 * BNH;
    float* outO     = out + BNK + 3 * BNH;

    const int s  = tid & 15;
    const int bg = tid >> 4;

    const int je = tid & 3;
    const int be = tid >> 2;
    const int cp = je >> 1, e = je & 1;
    const int bgi = be >> 2, bl = be & 3;

    // per-thread persistent cell state (this thread owns (col j0+je, batch be))
    float ct_r = 0.f, cbar_r = 0.f;

    for (int t = 0; t <= NEV; t++) {
        const int par = t & 1;
        const float* hbase = g_htb[par] + (size_t)(bg * 4) * HDIM;

        // ---------------- GEMM partials over 32 k (k = kk*16 + s) ----------------
        u64 acc[4][14];
        #pragma unroll
        for (int i = 0; i < 4; i++)
            #pragma unroll
            for (int p = 0; p < 14; p++) acc[i][p] = 0ull;
        u64 accL0 = 0ull, accL1 = 0ull;

        float hbuf[2][4];
        #pragma unroll
        for (int i = 0; i < 4; i++) hbuf[0][i] = __ldcg(hbase + i * HDIM + s);
        #pragma unroll
        for (int i = 0; i < 4; i++) hbuf[1][i] = __ldcg(hbase + i * HDIM + 16 + s);

        #pragma unroll 2
        for (int kk = 0; kk < 32; kk++) {
            float hc[4];
            #pragma unroll
            for (int i = 0; i < 4; i++) hc[i] = hbuf[kk & 1][i];
            if (kk < 30) {
                #pragma unroll
                for (int i = 0; i < 4; i++)
                    hbuf[kk & 1][i] = __ldcg(hbase + i * HDIM + (kk + 2) * 16 + s);
            }

            const int k = kk * 16 + s;
            const u64* wr = (const u64*)(w_sm + k * WST);
            u64 wv[14];
            #pragma unroll
            for (int p = 0; p < 14; p++) wv[p] = wr[p];
            float wl = w_sm[k * WST + 28];

            #pragma unroll
            for (int i = 0; i < 4; i++) {
                u64 hh = pack2(hc[i], hc[i]);
                #pragma unroll
                for (int p = 0; p < 14; p++)
                    acc[i][p] = ffma2(hh, wv[p], acc[i][p]);
            }
            u64 wld = pack2(wl, wl);
            accL0 = ffma2(pack2(hc[0], hc[1]), wld, accL0);
            accL1 = ffma2(pack2(hc[2], hc[3]), wld, accL1);
        }

        // ---------------- store partials ----------------
        {
            u64* pb = part + s * SST + bg;
            #pragma unroll
            for (int i = 0; i < 4; i++)
                #pragma unroll
                for (int p = 0; p < 14; p++)
                    pb[(i * 14 + p) * JST] = acc[i][p];
            pb[56 * JST] = accL0;
            pb[57 * JST] = accL1;
        }
        __syncthreads();

        // ---------------- reduce over 16 k-slices ----------------
        for (int r = tid; r < 928; r += NTH) {
            int j = r >> 4, bb = r & 15;
            const u64* pp = part + j * JST + bb;
            float sx = 0.f, sy = 0.f;
            #pragma unroll
            for (int ss = 0; ss < 16; ss++) {
                float2 v = unpack2(pp[ss * SST]);
                sx += v.x; sy += v.y;
            }
            gsum[r] = pack2(sx, sy);
        }
        __syncthreads();

        // ---------------- epilogue ----------------
        if (t >= 1 && je == 0) {
            float2 lp = unpack2(gsum[(56 + (bl >> 1)) * 16 + bgi]);
            float ltil = ((bl & 1) ? lp.y : lp.x) + bias_sm[28];
            float sc = bias_sm[29];
            float x = ltil / sc;
            float sp = fmaxf(x, 0.f) + log1pf(expf(-fabsf(x)));
            outLamb[((size_t)be * NEV + (t - 1)) * KDIM + c] = sc * sp;
        }

        if (t < NEV) {
            const int col = j0 + je;
            int   mark = g_marks[be * NEV + t];
            float dtv  = g_dt[be * NEV + t];
            const float* wu = W_U + (size_t)mark * G7;

            float gg[7];
            #pragma unroll
            for (int g = 0; g < 7; g++) {
                int p = g * 2 + cp;
                float2 v = unpack2(gsum[(bl * 14 + p) * 16 + bgi]);
                float a = e ? v.y : v.x;
                gg[g] = a + wu[g * HDIM + col] + bias_sm[p * 2 + e];
            }

            float vi  = sigf(gg[0]);
            float vf  = sigf(gg[1]);
            float viB = sigf(gg[2]);
            float vfB = sigf(gg[3]);
            float vz  = 2.0f * sigf(gg[4]);
            float vo  = sigf(gg[5]);
            float vd  = (gg[6] > 0.f) ? gg[6] : 0.01f * gg[6];

            float cl  = vf * ct_r + vi * vz;
            float cbn = vfB * cbar_r + viB * vz;
            float ctn = cbn + (cl - cbn) * expf(dtv * vd);
            float htn = vo * (2.0f * sigf(2.0f * ctn) - 1.0f);

            ct_r   = ctn;
            cbar_r = cbn;
            __stcg(&g_htb[par ^ 1][(size_t)be * HDIM + col], htn);

            size_t ob = ((size_t)be * NEV + t) * HDIM + col;
            outClow[ob]  = cl;
            outCbar[ob]  = cbn;
            outDelta[ob] = vd;
            outO[ob]     = vo;
        }

        // ---------------- grid barrier ----------------
        if (t < NEV) {
            __syncthreads();
            if (tid == 0) {
                __threadfence();
                unsigned tgt = (unsigned)(t + 1) * NCTA;
                unsigned prev = atomicAdd(&g_arrive, 1u);
                if (prev + 1u == tgt) {
                    atomicExch(&g_release, tgt);
                } else {
                    while (*((volatile unsigned*)&g_release) < tgt) { }
                }
                __threadfence();
            }
            __syncthreads();
        }
    }
}

// ---------------- launch ----------------
extern "C" void kernel_launch(void* const* d_in, const int* in_sizes, int n_in,
                              void* d_out, int out_size)
{
    const float* seq    = (const float*)d_in[0];
    const float* times  = (const float*)d_in[1];
    const float* W_U    = (const float*)d_in[2];
    const float* b_U    = (const float*)d_in[3];
    const float* W_V    = (const float*)d_in[4];
    const float* b_V    = (const float*)d_in[5];
    const float* W_lamb = (const float*)d_in[6];
    const float* b_lamb = (const float*)d_in[7];
    const float* scale  = (const float*)d_in[8];
    float* out = (float*)d_out;

    static int attr_done = 0;
    if (!attr_done) {
        cudaFuncSetAttribute(persist_kernel,
                             cudaFuncAttributeMaxDynamicSharedMemorySize, SMEM_TOT);
        attr_done = 1;
    }

    prep_kernel<<<64, 256>>>(seq, times);
    persist_kernel<<<NCTA, NTH, SMEM_TOT>>>(W_U, b_U, W_V, b_V,
                                            W_lamb, b_lamb, scale, out);
}

// round 6
// speedup vs baseline: 27.2350x; 1.8730x over previous
#include <cuda_runtime.h>
#include <cuda_bf16.h>
#include <math.h>
#include <stdint.h>

#define Bq    64
#define NEV   512
#define KDIM  128
#define HDIM  512
#define G7    3584
#define NCTA  128
#define NTH   256
#define GST   40            /* gsum row stride in floats */

// ---------------- SMEM layout (bytes, dynamic) ----------------
#define OFF_WF    0                      /* W frags: 2 spl x 4 nt x 32 ks x 256B = 65536 */
#define OFF_GSUM  65536                  /* 2 kh x 64 b x GST x 4B = 20480 */
#define OFF_BIAS  86016                  /* 32*4 */
#define SMEM_TOT  86144

// ---------------- persistent device scratch ----------------
__device__ int      g_marks[Bq * NEV];
__device__ float    g_dt[Bq * NEV];
// A fragments: [parity][split][mt(4)][ks(32)][lane(32)][reg(4)] u32 words (k-pairs of bf16)
__device__ uint32_t g_afrag[2][2][4 * 32 * 32 * 4];
__device__ unsigned g_arrive;
__device__ unsigned g_release;

// ---------------- helpers ----------------
__device__ __forceinline__ unsigned short bf_us(__nv_bfloat16 h) {
    return *reinterpret_cast<unsigned short*>(&h);
}
__device__ __forceinline__ float sigf(float x) { return 1.0f / (1.0f + expf(-x)); }

__device__ __forceinline__ void mma16816(float d[4],
                                         uint32_t a0, uint32_t a1, uint32_t a2, uint32_t a3,
                                         uint32_t b0, uint32_t b1) {
    asm volatile(
        "mma.sync.aligned.m16n8k16.row.col.f32.bf16.bf16.f32 "
        "{%0,%1,%2,%3}, {%4,%5,%6,%7}, {%8,%9}, {%0,%1,%2,%3};"
        : "+f"(d[0]), "+f"(d[1]), "+f"(d[2]), "+f"(d[3])
        : "r"(a0), "r"(a1), "r"(a2), "r"(a3), "r"(b0), "r"(b1));
}

// ---------------- prep ----------------
__global__ void prep_kernel(const float* __restrict__ seq,
                            const float* __restrict__ times)
{
    int tid = blockIdx.x * blockDim.x + threadIdx.x;
    int nt  = gridDim.x * blockDim.x;
    if (tid == 0) { g_arrive = 0u; g_release = 0u; }

    for (int i = tid; i < Bq * NEV; i += nt) {
        int b = i / NEV;
        int n = i - b * NEV;
        const float* s = seq + (size_t)i * KDIM;
        int m = 0;
        #pragma unroll 4
        for (int k = 0; k < KDIM; k++) if (s[k] > 0.5f) m = k;
        g_marks[i] = m;
        g_dt[i] = times[b * (NEV + 1) + n + 1] - times[b * (NEV + 1) + n];
    }
    // zero parity-0 A fragments (h_0 = 0); parity-1 gets fully written by step 0
    uint32_t* a0 = &g_afrag[0][0][0];
    for (int i = tid; i < 2 * 4 * 32 * 32 * 4; i += nt) a0[i] = 0u;
}

// ---------------- persistent kernel ----------------
// CTA c owns output cols n=0..27 (gate g=n>>2, state col j0+(n&3)) + lamb (n=28), pad 29-31.
// GEMM per step: D[64 batches x 32 n] = sum over K=512 of h(frag,global) x W(frag,smem),
// 3-term bf16 split, mma.sync m16n8k16. Warp w: m-tile mt=w>>1 (16 batches), k-half kh=w&1.
__global__ __launch_bounds__(NTH, 1) void persist_kernel(
    const float* __restrict__ W_U,  const float* __restrict__ b_U,
    const float* __restrict__ W_V,  const float* __restrict__ b_V,
    const float* __restrict__ W_lamb, const float* __restrict__ b_lamb,
    const float* __restrict__ scale,
    float* __restrict__ out)
{
    extern __shared__ char smem[];
    float* gsum    = (float*)(smem + OFF_GSUM);   // [2 kh][64 b][GST]
    float* bias_sm = (float*)(smem + OFF_BIAS);

    const int tid  = threadIdx.x;
    const int wid  = tid >> 5;
    const int lane = tid & 31;
    const int c    = blockIdx.x;
    const int j0   = c * 4;

    // ---- one-time: W slice -> bf16 hi/lo fragments in SMEM (B-frag layout) ----
    for (int idx = tid; idx < 32 * 512; idx += NTH) {
        int n = idx & 31, k = idx >> 5;
        float v = 0.f;
        if (n < 28)       v = W_V[(size_t)k * G7 + (n >> 2) * HDIM + j0 + (n & 3)];
        else if (n == 28) v = W_lamb[k * KDIM + c];
        __nv_bfloat16 hi = __float2bfloat16_rn(v);
        __nv_bfloat16 lo = __float2bfloat16_rn(v - __bfloat162float(hi));
        // B frag (col-major k16n8): lane = (n&7)*4 + ((k&7)>>1); reg = (k&15)>=8; byte = (k&1)*2
        int ntl = n >> 3, ks = k >> 4;
        int lw  = (n & 7) * 4 + ((k & 7) >> 1);
        int rg  = ((k & 15) >= 8) ? 1 : 0;
        int byt = (k & 1) * 2;
        *(unsigned short*)(smem + OFF_WF + ((0 * 4 + ntl) * 32 + ks) * 256 + lw * 8 + rg * 4 + byt) = bf_us(hi);
        *(unsigned short*)(smem + OFF_WF + ((1 * 4 + ntl) * 32 + ks) * 256 + lw * 8 + rg * 4 + byt) = bf_us(lo);
    }
    if (tid < 28) {
        int col = (tid >> 2) * HDIM + j0 + (tid & 3);
        bias_sm[tid] = b_U[col] + b_V[col];
    }
    if (tid == 28) bias_sm[28] = b_lamb[c];
    if (tid == 29) bias_sm[29] = scale[c];
    __syncthreads();

    // output views: lamb | CLow | Cbar | delta | OutGate
    const size_t BNK = (size_t)Bq * NEV * KDIM;
    const size_t BNH = (size_t)Bq * NEV * HDIM;
    float* outLamb  = out;
    float* outClow  = out + BNK;
    float* outCbar  = out + BNK + BNH;
    float* outDelta = out + BNK + 2 * BNH;
    float* outO     = out + BNK + 3 * BNH;

    const int mt = wid >> 1;      // m-tile (16 batches)
    const int kh = wid & 1;       // k-half (16 ksteps)
    const int je = tid & 3;       // epilogue: state col
    const int be = tid >> 2;      // epilogue: batch
    float ct_r = 0.f, cbar_r = 0.f;

    for (int t = 0; t <= NEV; t++) {
        const int par = t & 1;

        // ---------------- GEMM: 16 ksteps x 4 ntiles x 3 split-terms ----------------
        float D[4][4];
        #pragma unroll
        for (int n = 0; n < 4; n++) { D[n][0] = 0.f; D[n][1] = 0.f; D[n][2] = 0.f; D[n][3] = 0.f; }

        // one kstep of A frags = 32 lanes * 4 u32 = 128 u32 = 32 uint4
        const uint4* pahi = (const uint4*)&g_afrag[par][0][((mt * 32 + kh * 16) * 32 + lane) * 4];
        const uint4* palo = (const uint4*)&g_afrag[par][1][((mt * 32 + kh * 16) * 32 + lane) * 4];
        uint4 cahi = __ldcg(pahi);
        uint4 calo = __ldcg(palo);

        #pragma unroll
        for (int k16 = 0; k16 < 16; k16++) {
            uint4 nhi, nlo;
            if (k16 < 15) {                       // prefetch next kstep's A frags
                nhi = __ldcg(pahi + (k16 + 1) * 32);
                nlo = __ldcg(palo + (k16 + 1) * 32);
            }
            const int ks = kh * 16 + k16;
            #pragma unroll
            for (int nt = 0; nt < 4; nt++) {
                uint2 whi = *(const uint2*)(smem + OFF_WF + ((0 * 4 + nt) * 32 + ks) * 256 + lane * 8);
                uint2 wlo = *(const uint2*)(smem + OFF_WF + ((1 * 4 + nt) * 32 + ks) * 256 + lane * 8);
                mma16816(D[nt], cahi.x, cahi.y, cahi.z, cahi.w, whi.x, whi.y);
                mma16816(D[nt], cahi.x, cahi.y, cahi.z, cahi.w, wlo.x, wlo.y);
                mma16816(D[nt], calo.x, calo.y, calo.z, calo.w, whi.x, whi.y);
            }
            if (k16 < 15) { cahi = nhi; calo = nlo; }
        }

        // ---------------- store D to gsum (per k-half) ----------------
        {
            int b0 = mt * 16 + (lane >> 2);
            int n0 = (lane & 3) * 2;
            #pragma unroll
            for (int nt = 0; nt < 4; nt++) {
                float* p0 = gsum + (kh * 64 + b0) * GST + nt * 8 + n0;
                *(float2*)p0              = make_float2(D[nt][0], D[nt][1]);
                *(float2*)(p0 + 8 * GST)  = make_float2(D[nt][2], D[nt][3]);
            }
        }
        __syncthreads();

        // ---------------- epilogue ----------------
        if (t >= 1 && je == 0) {
            float ltil = gsum[be * GST + 28] + gsum[(64 + be) * GST + 28] + bias_sm[28];
            float sc = bias_sm[29];
            float x = ltil / sc;
            float sp = fmaxf(x, 0.f) + log1pf(expf(-fabsf(x)));
            outLamb[((size_t)be * NEV + (t - 1)) * KDIM + c] = sc * sp;
        }

        if (t < NEV) {
            const int col = j0 + je;
            int   mark = g_marks[be * NEV + t];
            float dtv  = g_dt[be * NEV + t];
            const float* wu = W_U + (size_t)mark * G7;

            float gg[7];
            #pragma unroll
            for (int g = 0; g < 7; g++) {
                int n = g * 4 + je;
                gg[g] = gsum[be * GST + n] + gsum[(64 + be) * GST + n]
                      + wu[g * HDIM + col] + bias_sm[n];
            }

            float vi  = sigf(gg[0]);
            float vf  = sigf(gg[1]);
            float viB = sigf(gg[2]);
            float vfB = sigf(gg[3]);
            float vz  = 2.0f * sigf(gg[4]);
            float vo  = sigf(gg[5]);
            float vd  = (gg[6] > 0.f) ? gg[6] : 0.01f * gg[6];

            float cl  = vf * ct_r + vi * vz;
            float cbn = vfB * cbar_r + viB * vz;
            float ctn = cbn + (cl - cbn) * expf(dtv * vd);
            float htn = vo * (2.0f * sigf(2.0f * ctn) - 1.0f);

            ct_r   = ctn;
            cbar_r = cbn;

            // ---- write h_{t} directly into A-fragment layout (global) ----
            __nv_bfloat16 hhi = __float2bfloat16_rn(htn);
            __nv_bfloat16 hlo = __float2bfloat16_rn(htn - __bfloat162float(hhi));
            uint32_t mine = (uint32_t)bf_us(hhi) | ((uint32_t)bf_us(hlo) << 16);
            uint32_t got  = __shfl_xor_sync(0xffffffffu, mine, 1);
            if ((je & 1) == 0) {
                uint32_t whiw = (mine & 0xffffu) | (got << 16);          // (my hi, partner hi)
                uint32_t wlow = (mine >> 16) | (got & 0xffff0000u);      // (my lo, partner lo)
                int p   = 2 * c + (je >> 1);     // k-pair index (k = col = j0+je)
                int mtb = be >> 4, r = be & 15;
                int ksb = p >> 3;
                int lw  = (r & 7) * 4 + (p & 3);
                int rg  = (r >> 3) + ((p >> 2) & 1) * 2;
                int widx = ((mtb * 32 + ksb) * 32 + lw) * 4 + rg;
                __stcg(&g_afrag[par ^ 1][0][widx], whiw);
                __stcg(&g_afrag[par ^ 1][1][widx], wlow);
            }

            size_t ob = ((size_t)be * NEV + t) * HDIM + col;
            outClow[ob]  = cl;
            outCbar[ob]  = cbn;
            outDelta[ob] = vd;
            outO[ob]     = vo;
        }

        // ---------------- grid barrier ----------------
        if (t < NEV) {
            __syncthreads();
            if (tid == 0) {
                __threadfence();
                unsigned tgt = (unsigned)(t + 1) * NCTA;
                unsigned prev = atomicAdd(&g_arrive, 1u);
                if (prev + 1u == tgt) {
                    atomicExch(&g_release, tgt);
                } else {
                    while (*((volatile unsigned*)&g_release) < tgt) { }
                }
                __threadfence();
            }
            __syncthreads();
        }
    }
}

// ---------------- launch ----------------
extern "C" void kernel_launch(void* const* d_in, const int* in_sizes, int n_in,
                              void* d_out, int out_size)
{
    const float* seq    = (const float*)d_in[0];
    const float* times  = (const float*)d_in[1];
    const float* W_U    = (const float*)d_in[2];
    const float* b_U    = (const float*)d_in[3];
    const float* W_V    = (const float*)d_in[4];
    const float* b_V    = (const float*)d_in[5];
    const float* W_lamb = (const float*)d_in[6];
    const float* b_lamb = (const float*)d_in[7];
    const float* scale  = (const float*)d_in[8];
    float* out = (float*)d_out;

    static int attr_done = 0;
    if (!attr_done) {
        cudaFuncSetAttribute(persist_kernel,
                             cudaFuncAttributeMaxDynamicSharedMemorySize, SMEM_TOT);
        attr_done = 1;
    }

    prep_kernel<<<64, 256>>>(seq, times);
    persist_kernel<<<NCTA, NTH, SMEM_TOT>>>(W_U, b_U, W_V, b_V,
                                            W_lamb, b_lamb, scale, out);
}

// round 7
// speedup vs baseline: 34.8151x; 1.2783x over previous
#include <cuda_runtime.h>
#include <cuda_bf16.h>
#include <math.h>
#include <stdint.h>

#define Bq    64
#define NEV   512
#define KDIM  128
#define HDIM  512
#define G7    3584
#define NCTA  128
#define NTH   256
#define GST   40            /* gsum row stride in floats */

// ---------------- SMEM layout (bytes, dynamic) ----------------
#define OFF_WF    0                      /* W frags: 2 spl x 4 nt x 32 ks x 256B = 65536 */
#define OFF_GSUM  65536                  /* 2 kh x 64 b x GST x 4B = 20480 */
#define OFF_BIAS  86016                  /* 32*4 */
#define SMEM_TOT  86144

// ---------------- persistent device scratch ----------------
__device__ int      g_marks[Bq * NEV];
__device__ float    g_dt[Bq * NEV];
// A fragments: [parity][split][mt(4)][ks(32)][lane(32)][reg(4)] u32 words (k-pairs of bf16)
__device__ uint32_t g_afrag[2][2][4 * 32 * 32 * 4];
__device__ unsigned g_arrive;

// ---------------- helpers ----------------
__device__ __forceinline__ unsigned short bf_us(__nv_bfloat16 h) {
    return *reinterpret_cast<unsigned short*>(&h);
}
__device__ __forceinline__ float sigf(float x) { return 1.0f / (1.0f + expf(-x)); }

__device__ __forceinline__ void mma16816(float d[4],
                                         uint32_t a0, uint32_t a1, uint32_t a2, uint32_t a3,
                                         uint32_t b0, uint32_t b1) {
    asm volatile(
        "mma.sync.aligned.m16n8k16.row.col.f32.bf16.bf16.f32 "
        "{%0,%1,%2,%3}, {%4,%5,%6,%7}, {%8,%9}, {%0,%1,%2,%3};"
        : "+f"(d[0]), "+f"(d[1]), "+f"(d[2]), "+f"(d[3])
        : "r"(a0), "r"(a1), "r"(a2), "r"(a3), "r"(b0), "r"(b1));
}

__device__ __forceinline__ void bar_arrive() {
    asm volatile("red.release.gpu.add.u32 [%0], %1;"
                 :: "l"(&g_arrive), "r"(1u) : "memory");
}
__device__ __forceinline__ void bar_poll(unsigned tgt) {
    unsigned v;
    do {
        asm volatile("ld.acquire.gpu.u32 %0, [%1];"
                     : "=r"(v) : "l"(&g_arrive) : "memory");
    } while (v < tgt);
}

// ---------------- prep ----------------
__global__ void prep_kernel(const float* __restrict__ seq,
                            const float* __restrict__ times)
{
    int tid = blockIdx.x * blockDim.x + threadIdx.x;
    int nt  = gridDim.x * blockDim.x;
    if (tid == 0) g_arrive = 0u;

    for (int i = tid; i < Bq * NEV; i += nt) {
        int b = i / NEV;
        int n = i - b * NEV;
        const float* s = seq + (size_t)i * KDIM;
        int m = 0;
        #pragma unroll 4
        for (int k = 0; k < KDIM; k++) if (s[k] > 0.5f) m = k;
        g_marks[i] = m;
        g_dt[i] = times[b * (NEV + 1) + n + 1] - times[b * (NEV + 1) + n];
    }
    // zero parity-0 A fragments (h_0 = 0)
    uint32_t* a0 = &g_afrag[0][0][0];
    for (int i = tid; i < 2 * 4 * 32 * 32 * 4; i += nt) a0[i] = 0u;
}

// ---------------- persistent kernel ----------------
__global__ __launch_bounds__(NTH, 1) void persist_kernel(
    const float* __restrict__ W_U,  const float* __restrict__ b_U,
    const float* __restrict__ W_V,  const float* __restrict__ b_V,
    const float* __restrict__ W_lamb, const float* __restrict__ b_lamb,
    const float* __restrict__ scale,
    float* __restrict__ out)
{
    extern __shared__ char smem[];
    float* gsum    = (float*)(smem + OFF_GSUM);   // [2 kh][64 b][GST]
    float* bias_sm = (float*)(smem + OFF_BIAS);

    const int tid  = threadIdx.x;
    const int wid  = tid >> 5;
    const int lane = tid & 31;
    const int c    = blockIdx.x;
    const int j0   = c * 4;

    // ---- one-time: W slice -> bf16 hi/lo fragments in SMEM (B-frag layout) ----
    for (int idx = tid; idx < 32 * 512; idx += NTH) {
        int n = idx & 31, k = idx >> 5;
        float v = 0.f;
        if (n < 28)       v = W_V[(size_t)k * G7 + (n >> 2) * HDIM + j0 + (n & 3)];
        else if (n == 28) v = W_lamb[k * KDIM + c];
        __nv_bfloat16 hi = __float2bfloat16_rn(v);
        __nv_bfloat16 lo = __float2bfloat16_rn(v - __bfloat162float(hi));
        int ntl = n >> 3, ks = k >> 4;
        int lw  = (n & 7) * 4 + ((k & 7) >> 1);
        int rg  = ((k & 15) >= 8) ? 1 : 0;
        int byt = (k & 1) * 2;
        *(unsigned short*)(smem + OFF_WF + ((0 * 4 + ntl) * 32 + ks) * 256 + lw * 8 + rg * 4 + byt) = bf_us(hi);
        *(unsigned short*)(smem + OFF_WF + ((1 * 4 + ntl) * 32 + ks) * 256 + lw * 8 + rg * 4 + byt) = bf_us(lo);
    }
    if (tid < 28) {
        int col = (tid >> 2) * HDIM + j0 + (tid & 3);
        bias_sm[tid] = b_U[col] + b_V[col];
    }
    if (tid == 28) bias_sm[28] = b_lamb[c];
    if (tid == 29) bias_sm[29] = scale[c];
    __syncthreads();

    // output views: lamb | CLow | Cbar | delta | OutGate
    const size_t BNK = (size_t)Bq * NEV * KDIM;
    const size_t BNH = (size_t)Bq * NEV * HDIM;
    float* outLamb  = out;
    float* outClow  = out + BNK;
    float* outCbar  = out + BNK + BNH;
    float* outDelta = out + BNK + 2 * BNH;
    float* outO     = out + BNK + 3 * BNH;

    const int mt = wid >> 1;      // m-tile (16 batches)
    const int kh = wid & 1;       // k-half (16 ksteps)
    const int je = tid & 3;       // epilogue: state col
    const int be = tid >> 2;      // epilogue: batch
    const int col = j0 + je;
    float ct_r = 0.f, cbar_r = 0.f;

    // ---- prefetch step-0 epilogue operands ----
    float wu_r[7], dt_r = 0.f;
    {
        int mark = g_marks[be * NEV + 0];
        dt_r = g_dt[be * NEV + 0];
        const float* wu = W_U + (size_t)mark * G7;
        #pragma unroll
        for (int g = 0; g < 7; g++) wu_r[g] = __ldg(&wu[g * HDIM + col]);
    }

    for (int t = 0; t <= NEV; t++) {
        const int par = t & 1;

        // ---------------- GEMM: batch-4 double-buffered A, 3-term bf16 split ----------------
        float D[4][4];
        #pragma unroll
        for (int n = 0; n < 4; n++) { D[n][0] = 0.f; D[n][1] = 0.f; D[n][2] = 0.f; D[n][3] = 0.f; }

        // one kstep of A frags = 32 uint4
        const uint4* pahi = (const uint4*)&g_afrag[par][0][((mt * 32 + kh * 16) * 32 + lane) * 4];
        const uint4* palo = (const uint4*)&g_afrag[par][1][((mt * 32 + kh * 16) * 32 + lane) * 4];

        uint4 bh[2][4], bl[2][4];
        #pragma unroll
        for (int i = 0; i < 4; i++) {
            bh[0][i] = __ldcg(pahi + i * 32);
            bl[0][i] = __ldcg(palo + i * 32);
        }

        #pragma unroll
        for (int grp = 0; grp < 4; grp++) {
            const int cur = grp & 1, nxt = cur ^ 1;
            if (grp < 3) {
                #pragma unroll
                for (int i = 0; i < 4; i++) {
                    bh[nxt][i] = __ldcg(pahi + ((grp + 1) * 4 + i) * 32);
                    bl[nxt][i] = __ldcg(palo + ((grp + 1) * 4 + i) * 32);
                }
            }
            #pragma unroll
            for (int k4 = 0; k4 < 4; k4++) {
                const int ks = kh * 16 + grp * 4 + k4;
                const uint4 ah = bh[cur][k4];
                const uint4 al = bl[cur][k4];
                #pragma unroll
                for (int nt = 0; nt < 4; nt++) {
                    uint2 whi = *(const uint2*)(smem + OFF_WF + ((0 * 4 + nt) * 32 + ks) * 256 + lane * 8);
                    uint2 wlo = *(const uint2*)(smem + OFF_WF + ((1 * 4 + nt) * 32 + ks) * 256 + lane * 8);
                    mma16816(D[nt], ah.x, ah.y, ah.z, ah.w, whi.x, whi.y);
                    mma16816(D[nt], ah.x, ah.y, ah.z, ah.w, wlo.x, wlo.y);
                    mma16816(D[nt], al.x, al.y, al.z, al.w, whi.x, whi.y);
                }
            }
        }

        // ---------------- store D to gsum ----------------
        {
            int b0 = mt * 16 + (lane >> 2);
            int n0 = (lane & 3) * 2;
            #pragma unroll
            for (int nt = 0; nt < 4; nt++) {
                float* p0 = gsum + (kh * 64 + b0) * GST + nt * 8 + n0;
                *(float2*)p0              = make_float2(D[nt][0], D[nt][1]);
                *(float2*)(p0 + 8 * GST)  = make_float2(D[nt][2], D[nt][3]);
            }
        }
        __syncthreads();

        // ---------------- epilogue: gate math + h-frag write (critical path) ----------------
        float cl = 0.f, cbn = 0.f, vd = 0.f, vo = 0.f;
        if (t < NEV) {
            float gg[7];
            #pragma unroll
            for (int g = 0; g < 7; g++) {
                int n = g * 4 + je;
                gg[g] = gsum[be * GST + n] + gsum[(64 + be) * GST + n]
                      + wu_r[g] + bias_sm[n];
            }

            float vi  = sigf(gg[0]);
            float vf  = sigf(gg[1]);
            float viB = sigf(gg[2]);
            float vfB = sigf(gg[3]);
            float vz  = 2.0f * sigf(gg[4]);
            vo  = sigf(gg[5]);
            vd  = (gg[6] > 0.f) ? gg[6] : 0.01f * gg[6];

            cl  = vf * ct_r + vi * vz;
            cbn = vfB * cbar_r + viB * vz;
            float ctn = cbn + (cl - cbn) * expf(dt_r * vd);
            float htn = vo * (2.0f * sigf(2.0f * ctn) - 1.0f);

            ct_r   = ctn;
            cbar_r = cbn;

            // write h_t into A-fragment layout for step t+1
            __nv_bfloat16 hhi = __float2bfloat16_rn(htn);
            __nv_bfloat16 hlo = __float2bfloat16_rn(htn - __bfloat162float(hhi));
            uint32_t mine = (uint32_t)bf_us(hhi) | ((uint32_t)bf_us(hlo) << 16);
            uint32_t got  = __shfl_xor_sync(0xffffffffu, mine, 1);
            if ((je & 1) == 0) {
                uint32_t whiw = (mine & 0xffffu) | (got << 16);
                uint32_t wlow = (mine >> 16) | (got & 0xffff0000u);
                int p   = 2 * c + (je >> 1);
                int mtb = be >> 4, r = be & 15;
                int ksb = p >> 3;
                int lw  = (r & 7) * 4 + (p & 3);
                int rg  = (r >> 3) + ((p >> 2) & 1) * 2;
                int widx = ((mtb * 32 + ksb) * 32 + lw) * 4 + rg;
                __stcg(&g_afrag[par ^ 1][0][widx], whiw);
                __stcg(&g_afrag[par ^ 1][1][widx], wlow);
            }
        }
        __syncthreads();           // all h-frag writes issued before release-arrive

        // ---------------- arrive, then overlap wait with outputs + prefetch ----------------
        if (t < NEV && tid == 0) bar_arrive();

        if (t >= 1 && je == 0) {
            float ltil = gsum[be * GST + 28] + gsum[(64 + be) * GST + 28] + bias_sm[28];
            float sc = bias_sm[29];
            float x = ltil / sc;
            float sp = fmaxf(x, 0.f) + log1pf(expf(-fabsf(x)));
            outLamb[((size_t)be * NEV + (t - 1)) * KDIM + c] = sc * sp;
        }

        if (t < NEV) {
            size_t ob = ((size_t)be * NEV + t) * HDIM + col;
            outClow[ob]  = cl;
            outCbar[ob]  = cbn;
            outDelta[ob] = vd;
            outO[ob]     = vo;

            // prefetch next step's epilogue operands (overlaps barrier wait)
            if (t + 1 < NEV) {
                int mark = g_marks[be * NEV + (t + 1)];
                dt_r = g_dt[be * NEV + (t + 1)];
                const float* wu = W_U + (size_t)mark * G7;
                #pragma unroll
                for (int g = 0; g < 7; g++) wu_r[g] = __ldg(&wu[g * HDIM + col]);
            }

            if (tid == 0) bar_poll((unsigned)(t + 1) * NCTA);
            __syncthreads();
        }
    }
}

// ---------------- launch ----------------
extern "C" void kernel_launch(void* const* d_in, const int* in_sizes, int n_in,
                              void* d_out, int out_size)
{
    const float* seq    = (const float*)d_in[0];
    const float* times  = (const float*)d_in[1];
    const float* W_U    = (const float*)d_in[2];
    const float* b_U    = (const float*)d_in[3];
    const float* W_V    = (const float*)d_in[4];
    const float* b_V    = (const float*)d_in[5];
    const float* W_lamb = (const float*)d_in[6];
    const float* b_lamb = (const float*)d_in[7];
    const float* scale  = (const float*)d_in[8];
    float* out = (float*)d_out;

    static int attr_done = 0;
    if (!attr_done) {
        cudaFuncSetAttribute(persist_kernel,
                             cudaFuncAttributeMaxDynamicSharedMemorySize, SMEM_TOT);
        attr_done = 1;
    }

    prep_kernel<<<64, 256>>>(seq, times);
    persist_kernel<<<NCTA, NTH, SMEM_TOT>>>(W_U, b_U, W_V, b_V,
                                            W_lamb, b_lamb, scale, out);
}

// round 8
// speedup vs baseline: 37.5328x; 1.0781x over previous
#include <cuda_runtime.h>
#include <cuda_bf16.h>
#include <math.h>
#include <stdint.h>

#define Bq    64
#define NEV   512
#define KDIM  128
#define HDIM  512
#define G7    3584
#define NCTA  128
#define NTH   256
#define GST   40            /* gsum row stride in floats */

// ---------------- SMEM layout (bytes, dynamic) ----------------
#define OFF_WF    0                      /* W frags: 2 spl x 4 nt x 32 ks x 256B = 65536 */
#define OFF_GSUM  65536                  /* 2 kh x 64 b x GST x 4B = 20480 */
#define OFF_BIAS  86016                  /* 32*4 */
#define SMEM_TOT  86144

// ---------------- persistent device scratch ----------------
__device__ int      g_marks[Bq * NEV];
__device__ float    g_dt[Bq * NEV];
// A fragments: [parity][split][mt(4)][ks(32)][lane(32)][reg(4)] u32 words (k-pairs of bf16)
__device__ uint32_t g_afrag[2][2][4 * 32 * 32 * 4];
__device__ unsigned g_flags[NCTA * 32];   // per-CTA epoch flags, 128B apart

// ---------------- helpers ----------------
__device__ __forceinline__ unsigned short bf_us(__nv_bfloat16 h) {
    return *reinterpret_cast<unsigned short*>(&h);
}
__device__ __forceinline__ float sigf(float x) {
    return __fdividef(1.0f, 1.0f + __expf(-x));
}

__device__ __forceinline__ void mma16816(float d[4],
                                         uint32_t a0, uint32_t a1, uint32_t a2, uint32_t a3,
                                         uint32_t b0, uint32_t b1) {
    asm volatile(
        "mma.sync.aligned.m16n8k16.row.col.f32.bf16.bf16.f32 "
        "{%0,%1,%2,%3}, {%4,%5,%6,%7}, {%8,%9}, {%0,%1,%2,%3};"
        : "+f"(d[0]), "+f"(d[1]), "+f"(d[2]), "+f"(d[3])
        : "r"(a0), "r"(a1), "r"(a2), "r"(a3), "r"(b0), "r"(b1));
}

// ---------------- prep ----------------
__global__ void prep_kernel(const float* __restrict__ seq,
                            const float* __restrict__ times)
{
    int tid = blockIdx.x * blockDim.x + threadIdx.x;
    int nt  = gridDim.x * blockDim.x;

    for (int i = tid; i < NCTA * 32; i += nt) g_flags[i] = 0u;

    for (int i = tid; i < Bq * NEV; i += nt) {
        int b = i / NEV;
        int n = i - b * NEV;
        const float* s = seq + (size_t)i * KDIM;
        int m = 0;
        #pragma unroll 4
        for (int k = 0; k < KDIM; k++) if (s[k] > 0.5f) m = k;
        g_marks[i] = m;
        g_dt[i] = times[b * (NEV + 1) + n + 1] - times[b * (NEV + 1) + n];
    }
    // zero parity-0 A fragments (h_0 = 0)
    uint32_t* a0 = &g_afrag[0][0][0];
    for (int i = tid; i < 2 * 4 * 32 * 32 * 4; i += nt) a0[i] = 0u;
}

// ---------------- persistent kernel ----------------
__global__ __launch_bounds__(NTH, 1) void persist_kernel(
    const float* __restrict__ W_U,  const float* __restrict__ b_U,
    const float* __restrict__ W_V,  const float* __restrict__ b_V,
    const float* __restrict__ W_lamb, const float* __restrict__ b_lamb,
    const float* __restrict__ scale,
    float* __restrict__ out)
{
    extern __shared__ char smem[];
    float* gsum    = (float*)(smem + OFF_GSUM);   // [2 kh][64 b][GST]
    float* bias_sm = (float*)(smem + OFF_BIAS);

    const int tid  = threadIdx.x;
    const int wid  = tid >> 5;
    const int lane = tid & 31;
    const int c    = blockIdx.x;
    const int j0   = c * 4;

    // ---- one-time: W slice -> bf16 hi/lo fragments in SMEM (B-frag layout) ----
    for (int idx = tid; idx < 32 * 512; idx += NTH) {
        int n = idx & 31, k = idx >> 5;
        float v = 0.f;
        if (n < 28)       v = W_V[(size_t)k * G7 + (n >> 2) * HDIM + j0 + (n & 3)];
        else if (n == 28) v = W_lamb[k * KDIM + c];
        __nv_bfloat16 hi = __float2bfloat16_rn(v);
        __nv_bfloat16 lo = __float2bfloat16_rn(v - __bfloat162float(hi));
        int ntl = n >> 3, ks = k >> 4;
        int lw  = (n & 7) * 4 + ((k & 7) >> 1);
        int rg  = ((k & 15) >= 8) ? 1 : 0;
        int byt = (k & 1) * 2;
        *(unsigned short*)(smem + OFF_WF + ((0 * 4 + ntl) * 32 + ks) * 256 + lw * 8 + rg * 4 + byt) = bf_us(hi);
        *(unsigned short*)(smem + OFF_WF + ((1 * 4 + ntl) * 32 + ks) * 256 + lw * 8 + rg * 4 + byt) = bf_us(lo);
    }
    if (tid < 28) {
        int col = (tid >> 2) * HDIM + j0 + (tid & 3);
        bias_sm[tid] = b_U[col] + b_V[col];
    }
    if (tid == 28) bias_sm[28] = b_lamb[c];
    if (tid == 29) bias_sm[29] = scale[c];
    __syncthreads();

    // output views: lamb | CLow | Cbar | delta | OutGate
    const size_t BNK = (size_t)Bq * NEV * KDIM;
    const size_t BNH = (size_t)Bq * NEV * HDIM;
    float* outLamb  = out;
    float* outClow  = out + BNK;
    float* outCbar  = out + BNK + BNH;
    float* outDelta = out + BNK + 2 * BNH;
    float* outO     = out + BNK + 3 * BNH;

    const int mt = wid >> 1;      // m-tile (16 batches)
    const int kh = wid & 1;       // k-half (16 ksteps)
    const int je = tid & 3;       // epilogue: state col
    const int be = tid >> 2;      // epilogue: batch
    const int col = j0 + je;
    float ct_r = 0.f, cbar_r = 0.f;

    // ---- prefetch step-0 epilogue operands ----
    float wu_r[7], dt_r = 0.f;
    {
        int mark = g_marks[be * NEV + 0];
        dt_r = g_dt[be * NEV + 0];
        const float* wu = W_U + (size_t)mark * G7;
        #pragma unroll
        for (int g = 0; g < 7; g++) wu_r[g] = __ldg(&wu[g * HDIM + col]);
    }

    for (int t = 0; t <= NEV; t++) {
        const int par = t & 1;

        // ---------------- GEMM: triple-buffered A, 3-term bf16 split ----------------
        float D[4][4];
        #pragma unroll
        for (int n = 0; n < 4; n++) { D[n][0] = 0.f; D[n][1] = 0.f; D[n][2] = 0.f; D[n][3] = 0.f; }

        // one kstep of A frags = 32 uint4
        const uint4* pahi = (const uint4*)&g_afrag[par][0][((mt * 32 + kh * 16) * 32 + lane) * 4];
        const uint4* palo = (const uint4*)&g_afrag[par][1][((mt * 32 + kh * 16) * 32 + lane) * 4];

        uint4 bh[3][4], bl[3][4];
        #pragma unroll
        for (int i = 0; i < 4; i++) {
            bh[0][i] = __ldcg(pahi + i * 32);
            bl[0][i] = __ldcg(palo + i * 32);
        }
        #pragma unroll
        for (int i = 0; i < 4; i++) {
            bh[1][i] = __ldcg(pahi + (4 + i) * 32);
            bl[1][i] = __ldcg(palo + (4 + i) * 32);
        }

        #pragma unroll
        for (int grp = 0; grp < 4; grp++) {
            const int cur = grp % 3;
            if (grp < 2) {
                const int pf = (grp + 2) % 3;
                #pragma unroll
                for (int i = 0; i < 4; i++) {
                    bh[pf][i] = __ldcg(pahi + ((grp + 2) * 4 + i) * 32);
                    bl[pf][i] = __ldcg(palo + ((grp + 2) * 4 + i) * 32);
                }
            }
            #pragma unroll
            for (int k4 = 0; k4 < 4; k4++) {
                const int ks = kh * 16 + grp * 4 + k4;
                const uint4 ah = bh[cur][k4];
                const uint4 al = bl[cur][k4];
                #pragma unroll
                for (int nt = 0; nt < 4; nt++) {
                    uint2 whi = *(const uint2*)(smem + OFF_WF + ((0 * 4 + nt) * 32 + ks) * 256 + lane * 8);
                    uint2 wlo = *(const uint2*)(smem + OFF_WF + ((1 * 4 + nt) * 32 + ks) * 256 + lane * 8);
                    mma16816(D[nt], ah.x, ah.y, ah.z, ah.w, whi.x, whi.y);
                    mma16816(D[nt], ah.x, ah.y, ah.z, ah.w, wlo.x, wlo.y);
                    mma16816(D[nt], al.x, al.y, al.z, al.w, whi.x, whi.y);
                }
            }
        }

        // ---------------- store D to gsum ----------------
        {
            int b0 = mt * 16 + (lane >> 2);
            int n0 = (lane & 3) * 2;
            #pragma unroll
            for (int nt = 0; nt < 4; nt++) {
                float* p0 = gsum + (kh * 64 + b0) * GST + nt * 8 + n0;
                *(float2*)p0              = make_float2(D[nt][0], D[nt][1]);
                *(float2*)(p0 + 8 * GST)  = make_float2(D[nt][2], D[nt][3]);
            }
        }
        __syncthreads();

        // ---------------- epilogue: gate math + h-frag write (critical path) ----------------
        float cl = 0.f, cbn = 0.f, vd = 0.f, vo = 0.f;
        if (t < NEV) {
            float gg[7];
            #pragma unroll
            for (int g = 0; g < 7; g++) {
                int n = g * 4 + je;
                gg[g] = gsum[be * GST + n] + gsum[(64 + be) * GST + n]
                      + wu_r[g] + bias_sm[n];
            }

            float vi  = sigf(gg[0]);
            float vf  = sigf(gg[1]);
            float viB = sigf(gg[2]);
            float vfB = sigf(gg[3]);
            float vz  = 2.0f * sigf(gg[4]);
            vo  = sigf(gg[5]);
            vd  = (gg[6] > 0.f) ? gg[6] : 0.01f * gg[6];

            cl  = vf * ct_r + vi * vz;
            cbn = vfB * cbar_r + viB * vz;
            float ctn = cbn + (cl - cbn) * __expf(dt_r * vd);
            float htn = vo * (2.0f * sigf(2.0f * ctn) - 1.0f);

            ct_r   = ctn;
            cbar_r = cbn;

            // write h_t into A-fragment layout for step t+1
            __nv_bfloat16 hhi = __float2bfloat16_rn(htn);
            __nv_bfloat16 hlo = __float2bfloat16_rn(htn - __bfloat162float(hhi));
            uint32_t mine = (uint32_t)bf_us(hhi) | ((uint32_t)bf_us(hlo) << 16);
            uint32_t got  = __shfl_xor_sync(0xffffffffu, mine, 1);
            if ((je & 1) == 0) {
                uint32_t whiw = (mine & 0xffffu) | (got << 16);
                uint32_t wlow = (mine >> 16) | (got & 0xffff0000u);
                int p   = 2 * c + (je >> 1);
                int mtb = be >> 4, r = be & 15;
                int ksb = p >> 3;
                int lw  = (r & 7) * 4 + (p & 3);
                int rg  = (r >> 3) + ((p >> 2) & 1) * 2;
                int widx = ((mtb * 32 + ksb) * 32 + lw) * 4 + rg;
                __stcg(&g_afrag[par ^ 1][0][widx], whiw);
                __stcg(&g_afrag[par ^ 1][1][widx], wlow);
            }
        }
        __syncthreads();           // publish h-frag writes before release-arrive

        // ---------------- arrive (own flag, no contention) ----------------
        if (t < NEV && tid == 0) {
            asm volatile("st.release.gpu.u32 [%0], %1;"
                         :: "l"(&g_flags[c * 32]), "r"((unsigned)(t + 1)) : "memory");
        }

        // ---------------- overlap wait with outputs + next-step prefetch ----------------
        if (t >= 1 && je == 0) {
            float ltil = gsum[be * GST + 28] + gsum[(64 + be) * GST + 28] + bias_sm[28];
            float sc = bias_sm[29];
            float x = ltil / sc;
            float sp = fmaxf(x, 0.f) + log1pf(__expf(-fabsf(x)));
            outLamb[((size_t)be * NEV + (t - 1)) * KDIM + c] = sc * sp;
        }

        if (t < NEV) {
            size_t ob = ((size_t)be * NEV + t) * HDIM + col;
            outClow[ob]  = cl;
            outCbar[ob]  = cbn;
            outDelta[ob] = vd;
            outO[ob]     = vo;

            if (t + 1 < NEV) {
                int mark = g_marks[be * NEV + (t + 1)];
                dt_r = g_dt[be * NEV + (t + 1)];
                const float* wu = W_U + (size_t)mark * G7;
                #pragma unroll
                for (int g = 0; g < 7; g++) wu_r[g] = __ldg(&wu[g * HDIM + col]);
            }

            // ---------------- parallel poll: each thread watches one CTA flag ----------------
            if (tid < NCTA) {
                unsigned v;
                do {
                    asm volatile("ld.acquire.gpu.u32 %0, [%1];"
                                 : "=r"(v) : "l"(&g_flags[tid * 32]) : "memory");
                } while (v < (unsigned)(t + 1));
            }
            __syncthreads();
        }
    }
}

// ---------------- launch ----------------
extern "C" void kernel_launch(void* const* d_in, const int* in_sizes, int n_in,
                              void* d_out, int out_size)
{
    const float* seq    = (const float*)d_in[0];
    const float* times  = (const float*)d_in[1];
    const float* W_U    = (const float*)d_in[2];
    const float* b_U    = (const float*)d_in[3];
    const float* W_V    = (const float*)d_in[4];
    const float* b_V    = (const float*)d_in[5];
    const float* W_lamb = (const float*)d_in[6];
    const float* b_lamb = (const float*)d_in[7];
    const float* scale  = (const float*)d_in[8];
    float* out = (float*)d_out;

    static int attr_done = 0;
    if (!attr_done) {
        cudaFuncSetAttribute(persist_kernel,
                             cudaFuncAttributeMaxDynamicSharedMemorySize, SMEM_TOT);
        attr_done = 1;
    }

    prep_kernel<<<64, 256>>>(seq, times);
    persist_kernel<<<NCTA, NTH, SMEM_TOT>>>(W_U, b_U, W_V, b_V,
                                            W_lamb, b_lamb, scale, out);
}

// round 9
// speedup vs baseline: 40.6069x; 1.0819x over previous
#include <cuda_runtime.h>
#include <cuda_fp16.h>
#include <math.h>
#include <stdint.h>

#define Bq    64
#define NEV   512
#define KDIM  128
#define HDIM  512
#define G7    3584
#define NCTA  128
#define NTH   256
#define GST   40            /* gsum row stride in floats */
#define LO_SCALE 0.000244140625f   /* 2^-12 */

// ---------------- SMEM layout (bytes, dynamic) ----------------
#define OFF_WF    0                      /* W frags: 2 spl x 4 nt x 32 ks x 256B = 65536 */
#define OFF_GSUM  65536                  /* 2 kh x 64 b x GST x 4B = 20480 */
#define OFF_BIAS  86016                  /* 32*4 */
#define SMEM_TOT  86144

// ---------------- persistent device scratch ----------------
__device__ int      g_marks[Bq * NEV];
__device__ float    g_dt[Bq * NEV];
// A fragments: [parity][mt(4)][ks(32)][lane(32)][reg(4)] u32 words (k-pairs of fp16)
__device__ uint32_t g_afrag[2][4 * 32 * 32 * 4];
__device__ unsigned g_flags[NCTA * 32];   // per-CTA epoch flags, 128B apart

// ---------------- helpers ----------------
__device__ __forceinline__ float sigf(float x) {
    return __fdividef(1.0f, 1.0f + __expf(-x));
}

__device__ __forceinline__ void mma16816(float d[4],
                                         uint32_t a0, uint32_t a1, uint32_t a2, uint32_t a3,
                                         uint32_t b0, uint32_t b1) {
    asm volatile(
        "mma.sync.aligned.m16n8k16.row.col.f32.f16.f16.f32 "
        "{%0,%1,%2,%3}, {%4,%5,%6,%7}, {%8,%9}, {%0,%1,%2,%3};"
        : "+f"(d[0]), "+f"(d[1]), "+f"(d[2]), "+f"(d[3])
        : "r"(a0), "r"(a1), "r"(a2), "r"(a3), "r"(b0), "r"(b1));
}

// ---------------- prep ----------------
__global__ void prep_kernel(const float* __restrict__ seq,
                            const float* __restrict__ times)
{
    int tid = blockIdx.x * blockDim.x + threadIdx.x;
    int nt  = gridDim.x * blockDim.x;

    for (int i = tid; i < NCTA * 32; i += nt) g_flags[i] = 0u;

    for (int i = tid; i < Bq * NEV; i += nt) {
        int b = i / NEV;
        int n = i - b * NEV;
        const float* s = seq + (size_t)i * KDIM;
        int m = 0;
        #pragma unroll 4
        for (int k = 0; k < KDIM; k++) if (s[k] > 0.5f) m = k;
        g_marks[i] = m;
        g_dt[i] = times[b * (NEV + 1) + n + 1] - times[b * (NEV + 1) + n];
    }
    // zero parity-0 A fragments (h_0 = 0)
    uint32_t* a0 = &g_afrag[0][0];
    for (int i = tid; i < 2 * 4 * 32 * 32 * 4; i += nt) a0[i] = 0u;
}

// ---------------- persistent kernel ----------------
__global__ __launch_bounds__(NTH, 1) void persist_kernel(
    const float* __restrict__ W_U,  const float* __restrict__ b_U,
    const float* __restrict__ W_V,  const float* __restrict__ b_V,
    const float* __restrict__ W_lamb, const float* __restrict__ b_lamb,
    const float* __restrict__ scale,
    float* __restrict__ out)
{
    extern __shared__ char smem[];
    float* gsum    = (float*)(smem + OFF_GSUM);   // [2 kh][64 b][GST]
    float* bias_sm = (float*)(smem + OFF_BIAS);

    const int tid  = threadIdx.x;
    const int wid  = tid >> 5;
    const int lane = tid & 31;
    const int c    = blockIdx.x;
    const int j0   = c * 4;

    // ---- one-time: W slice -> fp16 hi + scaled-lo fragments in SMEM (B-frag layout) ----
    for (int idx = tid; idx < 32 * 512; idx += NTH) {
        int n = idx & 31, k = idx >> 5;
        float v = 0.f;
        if (n < 28)       v = W_V[(size_t)k * G7 + (n >> 2) * HDIM + j0 + (n & 3)];
        else if (n == 28) v = W_lamb[k * KDIM + c];
        __half hi = __float2half_rn(v);
        __half lo = __float2half_rn((v - __half2float(hi)) * 4096.0f);  // pre-scaled 2^12
        int ntl = n >> 3, ks = k >> 4;
        int lw  = (n & 7) * 4 + ((k & 7) >> 1);
        int rg  = ((k & 15) >= 8) ? 1 : 0;
        int byt = (k & 1) * 2;
        *(unsigned short*)(smem + OFF_WF + ((0 * 4 + ntl) * 32 + ks) * 256 + lw * 8 + rg * 4 + byt) = __half_as_ushort(hi);
        *(unsigned short*)(smem + OFF_WF + ((1 * 4 + ntl) * 32 + ks) * 256 + lw * 8 + rg * 4 + byt) = __half_as_ushort(lo);
    }
    if (tid < 28) {
        int col = (tid >> 2) * HDIM + j0 + (tid & 3);
        bias_sm[tid] = b_U[col] + b_V[col];
    }
    if (tid == 28) bias_sm[28] = b_lamb[c];
    if (tid == 29) bias_sm[29] = scale[c];
    __syncthreads();

    // output views: lamb | CLow | Cbar | delta | OutGate
    const size_t BNK = (size_t)Bq * NEV * KDIM;
    const size_t BNH = (size_t)Bq * NEV * HDIM;
    float* outLamb  = out;
    float* outClow  = out + BNK;
    float* outCbar  = out + BNK + BNH;
    float* outDelta = out + BNK + 2 * BNH;
    float* outO     = out + BNK + 3 * BNH;

    const int mt = wid >> 1;      // m-tile (16 batches)
    const int kh = wid & 1;       // k-half (16 ksteps)
    const int je = tid & 3;       // epilogue: state col
    const int be = tid >> 2;      // epilogue: batch
    const int col = j0 + je;
    float ct_r = 0.f, cbar_r = 0.f;

    // ---- prefetch step-0 epilogue operands ----
    float wu_r[7], dt_r = 0.f;
    {
        int mark = g_marks[be * NEV + 0];
        dt_r = g_dt[be * NEV + 0];
        const float* wu = W_U + (size_t)mark * G7;
        #pragma unroll
        for (int g = 0; g < 7; g++) wu_r[g] = __ldg(&wu[g * HDIM + col]);
    }

    for (int t = 0; t <= NEV; t++) {
        const int par = t & 1;

        // ---------------- GEMM: single fp16 A, 2-term W split, dual accumulators --------
        float D[4][4], Dl[4][4];
        #pragma unroll
        for (int n = 0; n < 4; n++) {
            D[n][0] = 0.f; D[n][1] = 0.f; D[n][2] = 0.f; D[n][3] = 0.f;
            Dl[n][0] = 0.f; Dl[n][1] = 0.f; Dl[n][2] = 0.f; Dl[n][3] = 0.f;
        }

        // one kstep of A frags = 32 uint4
        const uint4* pa = (const uint4*)&g_afrag[par][((mt * 32 + kh * 16) * 32 + lane) * 4];

        uint4 ab[3][4];
        #pragma unroll
        for (int i = 0; i < 4; i++) ab[0][i] = __ldcg(pa + i * 32);
        #pragma unroll
        for (int i = 0; i < 4; i++) ab[1][i] = __ldcg(pa + (4 + i) * 32);

        #pragma unroll
        for (int grp = 0; grp < 4; grp++) {
            const int cur = grp % 3;
            if (grp < 2) {
                const int pf = (grp + 2) % 3;
                #pragma unroll
                for (int i = 0; i < 4; i++)
                    ab[pf][i] = __ldcg(pa + ((grp + 2) * 4 + i) * 32);
            }
            #pragma unroll
            for (int k4 = 0; k4 < 4; k4++) {
                const int ks = kh * 16 + grp * 4 + k4;
                const uint4 a = ab[cur][k4];
                #pragma unroll
                for (int nt = 0; nt < 4; nt++) {
                    uint2 whi = *(const uint2*)(smem + OFF_WF + ((0 * 4 + nt) * 32 + ks) * 256 + lane * 8);
                    uint2 wlo = *(const uint2*)(smem + OFF_WF + ((1 * 4 + nt) * 32 + ks) * 256 + lane * 8);
                    mma16816(D[nt],  a.x, a.y, a.z, a.w, whi.x, whi.y);
                    mma16816(Dl[nt], a.x, a.y, a.z, a.w, wlo.x, wlo.y);
                }
            }
        }

        // ---------------- store D (+ scaled lo) to gsum ----------------
        {
            int b0 = mt * 16 + (lane >> 2);
            int n0 = (lane & 3) * 2;
            #pragma unroll
            for (int nt = 0; nt < 4; nt++) {
                float* p0 = gsum + (kh * 64 + b0) * GST + nt * 8 + n0;
                *(float2*)p0 = make_float2(fmaf(LO_SCALE, Dl[nt][0], D[nt][0]),
                                           fmaf(LO_SCALE, Dl[nt][1], D[nt][1]));
                *(float2*)(p0 + 8 * GST) = make_float2(fmaf(LO_SCALE, Dl[nt][2], D[nt][2]),
                                                       fmaf(LO_SCALE, Dl[nt][3], D[nt][3]));
            }
        }
        __syncthreads();

        // ---------------- epilogue: gate math + h-frag write (critical path) ----------------
        float cl = 0.f, cbn = 0.f, vd = 0.f, vo = 0.f;
        if (t < NEV) {
            float gg[7];
            #pragma unroll
            for (int g = 0; g < 7; g++) {
                int n = g * 4 + je;
                gg[g] = gsum[be * GST + n] + gsum[(64 + be) * GST + n]
                      + wu_r[g] + bias_sm[n];
            }

            float vi  = sigf(gg[0]);
            float vf  = sigf(gg[1]);
            float viB = sigf(gg[2]);
            float vfB = sigf(gg[3]);
            float vz  = 2.0f * sigf(gg[4]);
            vo  = sigf(gg[5]);
            vd  = (gg[6] > 0.f) ? gg[6] : 0.01f * gg[6];

            cl  = vf * ct_r + vi * vz;
            cbn = vfB * cbar_r + viB * vz;
            float ctn = cbn + (cl - cbn) * __expf(dt_r * vd);
            float htn = vo * (2.0f * sigf(2.0f * ctn) - 1.0f);

            ct_r   = ctn;
            cbar_r = cbn;

            // write h_t (single fp16) into A-fragment layout for step t+1
            uint32_t mine = (uint32_t)__half_as_ushort(__float2half_rn(htn));
            uint32_t got  = __shfl_xor_sync(0xffffffffu, mine, 1);
            if ((je & 1) == 0) {
                uint32_t word = (mine & 0xffffu) | (got << 16);
                int p   = 2 * c + (je >> 1);
                int mtb = be >> 4, r = be & 15;
                int ksb = p >> 3;
                int lw  = (r & 7) * 4 + (p & 3);
                int rg  = (r >> 3) + ((p >> 2) & 1) * 2;
                int widx = ((mtb * 32 + ksb) * 32 + lw) * 4 + rg;
                __stcg(&g_afrag[par ^ 1][widx], word);
            }
        }
        __syncthreads();           // publish h-frag writes before release-arrive

        // ---------------- arrive (own flag, no contention) ----------------
        if (t < NEV && tid == 0) {
            asm volatile("st.release.gpu.u32 [%0], %1;"
                         :: "l"(&g_flags[c * 32]), "r"((unsigned)(t + 1)) : "memory");
        }

        // ---------------- overlap wait with outputs + next-step prefetch ----------------
        if (t >= 1 && je == 0) {
            float ltil = gsum[be * GST + 28] + gsum[(64 + be) * GST + 28] + bias_sm[28];
            float sc = bias_sm[29];
            float x = ltil / sc;
            float sp = fmaxf(x, 0.f) + log1pf(__expf(-fabsf(x)));
            outLamb[((size_t)be * NEV + (t - 1)) * KDIM + c] = sc * sp;
        }

        if (t < NEV) {
            size_t ob = ((size_t)be * NEV + t) * HDIM + col;
            outClow[ob]  = cl;
            outCbar[ob]  = cbn;
            outDelta[ob] = vd;
            outO[ob]     = vo;

            if (t + 1 < NEV) {
                int mark = g_marks[be * NEV + (t + 1)];
                dt_r = g_dt[be * NEV + (t + 1)];
                const float* wu = W_U + (size_t)mark * G7;
                #pragma unroll
                for (int g = 0; g < 7; g++) wu_r[g] = __ldg(&wu[g * HDIM + col]);
            }

            // ---------------- parallel poll: each thread watches one CTA flag ----------------
            if (tid < NCTA) {
                unsigned v;
                do {
                    asm volatile("ld.acquire.gpu.u32 %0, [%1];"
                                 : "=r"(v) : "l"(&g_flags[tid * 32]) : "memory");
                } while (v < (unsigned)(t + 1));
            }
            __syncthreads();
        }
    }
}

// ---------------- launch ----------------
extern "C" void kernel_launch(void* const* d_in, const int* in_sizes, int n_in,
                              void* d_out, int out_size)
{
    const float* seq    = (const float*)d_in[0];
    const float* times  = (const float*)d_in[1];
    const float* W_U    = (const float*)d_in[2];
    const float* b_U    = (const float*)d_in[3];
    const float* W_V    = (const float*)d_in[4];
    const float* b_V    = (const float*)d_in[5];
    const float* W_lamb = (const float*)d_in[6];
    const float* b_lamb = (const float*)d_in[7];
    const float* scale  = (const float*)d_in[8];
    float* out = (float*)d_out;

    static int attr_done = 0;
    if (!attr_done) {
        cudaFuncSetAttribute(persist_kernel,
                             cudaFuncAttributeMaxDynamicSharedMemorySize, SMEM_TOT);
        attr_done = 1;
    }

    prep_kernel<<<64, 256>>>(seq, times);
    persist_kernel<<<NCTA, NTH, SMEM_TOT>>>(W_U, b_U, W_V, b_V,
                                            W_lamb, b_lamb, scale, out);
}